// round 4
// baseline (speedup 1.0000x reference)
#include <cuda_runtime.h>
#include <cuda_bf16.h>

#define THREADS 512
#define ITEMS   4
#define TILE    (THREADS * ITEMS)
#define NWARPS  (THREADS / 32)
#define MAXSLOTS 32768

// Write-once lookback state (per row-partition slot). NEVER overwritten.
//   g_tum[slot]: [flag:32 | tumble_count:32]  (flag: 0=invalid, 1=published)
//   g_fz [slot]: [flag:32 | fz_bits:32]
//   g_fxy[slot]: [fy_bits:32 | fx_bits:32]    (ordered via release on g_fz)
__device__ unsigned long long g_tum[MAXSLOTS];
__device__ unsigned long long g_fz [MAXSLOTS];
__device__ unsigned long long g_fxy[MAXSLOTS];

static __device__ __forceinline__ unsigned long long ld_acq(const unsigned long long* p) {
    unsigned long long v;
    asm volatile("ld.acquire.gpu.b64 %0, [%1];" : "=l"(v) : "l"(p) : "memory");
    return v;
}
static __device__ __forceinline__ void st_rel(unsigned long long* p, unsigned long long v) {
    asm volatile("st.release.gpu.b64 [%0], %1;" :: "l"(p), "l"(v) : "memory");
}
static __device__ __forceinline__ unsigned long long ld_rlx(const unsigned long long* p) {
    unsigned long long v;
    asm volatile("ld.relaxed.gpu.b64 %0, [%1];" : "=l"(v) : "l"(p) : "memory");
    return v;
}
static __device__ __forceinline__ void st_rlx(unsigned long long* p, unsigned long long v) {
    asm volatile("st.relaxed.gpu.b64 [%0], %1;" :: "l"(p), "l"(v) : "memory");
}

__global__ void init_flags(int n) {
    int i = blockIdx.x * blockDim.x + threadIdx.x;
    if (i < n) { g_tum[i] = 0ULL; g_fz[i] = 0ULL; }
}

__global__ __launch_bounds__(THREADS)
void traj_scan_kernel(const int*   __restrict__ states,
                      const float* __restrict__ e0s,
                      const float* __restrict__ speed0,
                      const float* __restrict__ speed1,
                      const float* __restrict__ x0,
                      float*       __restrict__ X,
                      int T, int P)
{
    const int p = blockIdx.x;          // partition within row (x = fastest)
    const int b = blockIdx.y;          // row
    const int slot  = b * P + p;
    const int sbase = b * P;

    const int*   srow = states + (size_t)b * T;
    const float* erow = e0s    + (size_t)b * (T + 1) * 3;
    float*       xrow = X      + (size_t)b * T * 3;

    const float sp0 = speed0[b];
    const float sp1 = speed1[b];
    const float DT  = 0.1f;

    __shared__ int   s_wi[NWARPS];
    __shared__ float s_wx[NWARPS], s_wy[NWARPS], s_wz[NWARPS];
    __shared__ int   s_texcl;
    __shared__ float s_fex, s_fey, s_fez;

    const int lane = threadIdx.x & 31;
    const int wid  = threadIdx.x >> 5;
    const int t0   = p * TILE + threadIdx.x * ITEMS;

    // ---- load states tile (vectorized when in-bounds) ----
    int st[ITEMS];
    if (t0 + ITEMS <= T) {
        int4 v = *reinterpret_cast<const int4*>(srow + t0);
        st[0] = v.x; st[1] = v.y; st[2] = v.z; st[3] = v.w;
    } else {
        #pragma unroll
        for (int i = 0; i < ITEMS; i++)
            st[i] = (t0 + i < T) ? srow[t0 + i] : 0;
    }

    // ---- thread-local inclusive tumble count ----
    int c[ITEMS];
    int run = 0;
    #pragma unroll
    for (int i = 0; i < ITEMS; i++) { run += (st[i] == 2); c[i] = run; }

    // ---- block scan of per-thread tumble sums ----
    int xs = run;
    #pragma unroll
    for (int d = 1; d < 32; d <<= 1) {
        int y = __shfl_up_sync(0xffffffffu, xs, d);
        if (lane >= d) xs += y;
    }
    if (lane == 31) s_wi[wid] = xs;
    __syncthreads();
    if (wid == 0) {
        int w = (lane < NWARPS) ? s_wi[lane] : 0;
        #pragma unroll
        for (int d = 1; d < 32; d <<= 1) {
            int y = __shfl_up_sync(0xffffffffu, w, d);
            if (lane >= d) w += y;
        }
        if (lane < NWARPS) s_wi[lane] = w;
    }
    __syncthreads();
    const int thr_texcl = (wid ? s_wi[wid - 1] : 0) + (xs - run);
    const int tile_tum  = s_wi[NWARPS - 1];

    // ---- publish tumble aggregate (write-once), then sum all predecessors ----
    if (threadIdx.x == 0)
        st_rel(&g_tum[slot], (1ULL << 32) | (unsigned)tile_tum);

    if (wid == 0) {
        int excl = 0;
        for (int we = p - 1; we >= 0; we -= 32) {
            const int idx = we - lane;
            unsigned val = 0;
            if (idx >= 0) {
                unsigned long long w;
                do { w = ld_acq(&g_tum[sbase + idx]); } while (!(w >> 32));
                val = (unsigned)w;
            }
            excl += (int)__reduce_add_sync(0xffffffffu, val);
        }
        if (lane == 0) s_texcl = excl;
    }
    __syncthreads();
    const int kbase = s_texcl + thr_texcl;

    // ---- gather e0s, build local inclusive float3 scan ----
    float vx[ITEMS], vy[ITEMS], vz[ITEMS];
    float ax = 0.f, ay = 0.f, az = 0.f;
    #pragma unroll
    for (int i = 0; i < ITEMS; i++) {
        const int t = t0 + i;
        if (t < T && st[i] != 2) {
            const int k = kbase + c[i];
            const float* e = erow + (size_t)k * 3;
            const float sp = (st[i] == 0) ? sp0 : sp1;
            ax = fmaf(__ldg(e + 0), sp, ax);
            ay = fmaf(__ldg(e + 1), sp, ay);
            az = fmaf(__ldg(e + 2), sp, az);
        }
        vx[i] = ax; vy[i] = ay; vz[i] = az;
    }

    // ---- block scan of per-thread float3 sums ----
    float sx = ax, sy = ay, sz = az;
    #pragma unroll
    for (int d = 1; d < 32; d <<= 1) {
        float tx = __shfl_up_sync(0xffffffffu, sx, d);
        float ty = __shfl_up_sync(0xffffffffu, sy, d);
        float tz = __shfl_up_sync(0xffffffffu, sz, d);
        if (lane >= d) { sx += tx; sy += ty; sz += tz; }
    }
    if (lane == 31) { s_wx[wid] = sx; s_wy[wid] = sy; s_wz[wid] = sz; }
    __syncthreads();
    if (wid == 0) {
        float wx = (lane < NWARPS) ? s_wx[lane] : 0.f;
        float wy = (lane < NWARPS) ? s_wy[lane] : 0.f;
        float wz = (lane < NWARPS) ? s_wz[lane] : 0.f;
        #pragma unroll
        for (int d = 1; d < 32; d <<= 1) {
            float tx = __shfl_up_sync(0xffffffffu, wx, d);
            float ty = __shfl_up_sync(0xffffffffu, wy, d);
            float tz = __shfl_up_sync(0xffffffffu, wz, d);
            if (lane >= d) { wx += tx; wy += ty; wz += tz; }
        }
        if (lane < NWARPS) { s_wx[lane] = wx; s_wy[lane] = wy; s_wz[lane] = wz; }
    }
    __syncthreads();
    float exl = (sx - ax), eyl = (sy - ay), ezl = (sz - az);
    if (wid) { exl += s_wx[wid - 1]; eyl += s_wy[wid - 1]; ezl += s_wz[wid - 1]; }
    const float totx = s_wx[NWARPS - 1];
    const float toty = s_wy[NWARPS - 1];
    const float totz = s_wz[NWARPS - 1];

    // ---- publish float aggregate (write-once), then sum all predecessors ----
    if (threadIdx.x == 0) {
        unsigned long long xy = ((unsigned long long)__float_as_uint(toty) << 32)
                               | __float_as_uint(totx);
        st_rlx(&g_fxy[slot], xy);                       // data first
        st_rel(&g_fz [slot], (1ULL << 32) | __float_as_uint(totz)); // then flag
    }
    if (wid == 0) {
        float fx = 0.f, fy = 0.f, fz = 0.f;
        for (int we = p - 1; we >= 0; we -= 32) {
            const int idx = we - lane;
            float px = 0.f, py = 0.f, pz = 0.f;
            if (idx >= 0) {
                unsigned long long w;
                do { w = ld_acq(&g_fz[sbase + idx]); } while (!(w >> 32));
                pz = __uint_as_float((unsigned)w);
                unsigned long long xy = ld_rlx(&g_fxy[sbase + idx]);
                px = __uint_as_float((unsigned)xy);
                py = __uint_as_float((unsigned)(xy >> 32));
            }
            #pragma unroll
            for (int d = 16; d; d >>= 1) {
                px += __shfl_down_sync(0xffffffffu, px, d);
                py += __shfl_down_sync(0xffffffffu, py, d);
                pz += __shfl_down_sync(0xffffffffu, pz, d);
            }
            fx += __shfl_sync(0xffffffffu, px, 0);
            fy += __shfl_sync(0xffffffffu, py, 0);
            fz += __shfl_sync(0xffffffffu, pz, 0);
        }
        if (lane == 0) { s_fex = fx; s_fey = fy; s_fez = fz; }
    }
    __syncthreads();

    const float ox = x0[3 * b + 0];
    const float oy = x0[3 * b + 1];
    const float oz = x0[3 * b + 2];
    const float ex = s_fex + exl;
    const float ey = s_fey + eyl;
    const float ez = s_fez + ezl;

    // ---- write output: 12 contiguous floats per thread (3x float4) ----
    if (t0 + ITEMS <= T) {
        float o[12];
        #pragma unroll
        for (int i = 0; i < ITEMS; i++) {
            o[3 * i + 0] = ox + DT * (ex + vx[i]);
            o[3 * i + 1] = oy + DT * (ey + vy[i]);
            o[3 * i + 2] = oz + DT * (ez + vz[i]);
        }
        float4* q = reinterpret_cast<float4*>(xrow + (size_t)t0 * 3);
        q[0] = make_float4(o[0], o[1], o[2],  o[3]);
        q[1] = make_float4(o[4], o[5], o[6],  o[7]);
        q[2] = make_float4(o[8], o[9], o[10], o[11]);
    } else {
        #pragma unroll
        for (int i = 0; i < ITEMS; i++) {
            const int t = t0 + i;
            if (t < T) {
                float* o = xrow + (size_t)t * 3;
                o[0] = ox + DT * (ex + vx[i]);
                o[1] = oy + DT * (ey + vy[i]);
                o[2] = oz + DT * (ez + vz[i]);
            }
        }
    }
}

extern "C" void kernel_launch(void* const* d_in, const int* in_sizes, int n_in,
                              void* d_out, int out_size)
{
    const int*   states = (const int*)  d_in[0];
    const float* e0s    = (const float*)d_in[1];
    const float* sp0    = (const float*)d_in[2];
    const float* sp1    = (const float*)d_in[3];
    const float* x0     = (const float*)d_in[4];
    float*       X      = (float*)d_out;

    const int B = in_sizes[2];           // speed_0 has B elements
    const int T = in_sizes[0] / B;       // states is (B, T)
    const int P = (T + TILE - 1) / TILE; // partitions per row

    const int n = B * P;
    init_flags<<<(n + 255) / 256, 256>>>(n);

    dim3 grid(P, B);
    traj_scan_kernel<<<grid, THREADS>>>(states, e0s, sp0, sp1, x0, X, T, P);
}

// round 5
// speedup vs baseline: 2.1200x; 2.1200x over previous
#include <cuda_runtime.h>
#include <cuda_bf16.h>

#define THREADS 512
#define ITEMS   8
#define CHUNK   (THREADS * ITEMS)   // 4096
#define NWARPS  (THREADS / 32)      // 16

__global__ __launch_bounds__(THREADS, 2)
void traj_scan_kernel(const int*   __restrict__ states,
                      const float* __restrict__ e0s,
                      const float* __restrict__ speed0,
                      const float* __restrict__ speed1,
                      const float* __restrict__ x0,
                      float*       __restrict__ X,
                      int T)
{
    const int b = blockIdx.x;
    const int*   srow = states + (size_t)b * T;
    const float* erow = e0s    + (size_t)b * (T + 1) * 3;
    float*       xrow = X      + (size_t)b * T * 3;

    const float sp0 = speed0[b];
    const float sp1 = speed1[b];
    const float ox = x0[3 * b + 0];
    const float oy = x0[3 * b + 1];
    const float oz = x0[3 * b + 2];
    const float DT = 0.1f;

    // parity double-buffered warp-total arrays (lets us drop trailing sync)
    __shared__ int   s_wi[2][NWARPS];
    __shared__ float s_wx[2][NWARPS], s_wy[2][NWARPS], s_wz[2][NWARPS];

    int   carry_k = 0;
    float carry_x = 0.f, carry_y = 0.f, carry_z = 0.f;

    const int lane = threadIdx.x & 31;
    const int wid  = threadIdx.x >> 5;

    // ---- prefetch first states tile ----
    int4 na = make_int4(0, 0, 0, 0), nb = make_int4(0, 0, 0, 0);
    {
        const int t0 = threadIdx.x * ITEMS;
        if (t0 + ITEMS <= T) {
            na = *reinterpret_cast<const int4*>(srow + t0);
            nb = *reinterpret_cast<const int4*>(srow + t0 + 4);
        } else {
            int tmp[8] = {0,0,0,0,0,0,0,0};
            #pragma unroll
            for (int i = 0; i < ITEMS; i++)
                if (t0 + i < T) tmp[i] = srow[t0 + i];
            na = make_int4(tmp[0], tmp[1], tmp[2], tmp[3]);
            nb = make_int4(tmp[4], tmp[5], tmp[6], tmp[7]);
        }
    }

    int buf = 0;
    for (int base = 0; base < T; base += CHUNK, buf ^= 1) {
        const int t0     = base + threadIdx.x * ITEMS;
        const int nvalid = max(0, min(ITEMS, T - t0));

        // consume prefetched tile into bitmasks, then immediately prefetch next
        int s[8] = { na.x, na.y, na.z, na.w, nb.x, nb.y, nb.z, nb.w };
        unsigned tmask = 0, s0mask = 0, c_packed = 0;
        int run = 0;
        #pragma unroll
        for (int i = 0; i < ITEMS; i++) {
            const unsigned isT = (s[i] == 2);
            const unsigned is0 = (s[i] == 0);
            tmask  |= isT << i;
            s0mask |= is0 << i;
            run += (int)isT;
            c_packed |= (unsigned)run << (4 * i);
        }

        const int nbase = base + CHUNK;
        if (nbase < T) {
            const int nt0 = nbase + threadIdx.x * ITEMS;
            if (nt0 + ITEMS <= T) {
                na = *reinterpret_cast<const int4*>(srow + nt0);
                nb = *reinterpret_cast<const int4*>(srow + nt0 + 4);
            } else {
                int tmp[8] = {0,0,0,0,0,0,0,0};
                #pragma unroll
                for (int i = 0; i < ITEMS; i++)
                    if (nt0 + i < T) tmp[i] = srow[nt0 + i];
                na = make_int4(tmp[0], tmp[1], tmp[2], tmp[3]);
                nb = make_int4(tmp[4], tmp[5], tmp[6], tmp[7]);
            }
        }

        // ---- block scan of per-thread tumble sums ----
        int xs = run;
        #pragma unroll
        for (int d = 1; d < 32; d <<= 1) {
            int y = __shfl_up_sync(0xffffffffu, xs, d);
            if (lane >= d) xs += y;
        }
        if (lane == 31) s_wi[buf][wid] = xs;
        __syncthreads();
        if (wid == 0) {
            int w = (lane < NWARPS) ? s_wi[buf][lane] : 0;
            #pragma unroll
            for (int d = 1; d < NWARPS; d <<= 1) {
                int y = __shfl_up_sync(0xffffffffu, w, d);
                if (lane >= d) w += y;
            }
            if (lane < NWARPS) s_wi[buf][lane] = w;
        }
        __syncthreads();
        const int thr_texcl = (wid ? s_wi[buf][wid - 1] : 0) + (xs - run);
        const int tile_tum  = s_wi[buf][NWARPS - 1];
        const int kbase     = carry_k + thr_texcl;

        // ---- gather e0s, local inclusive float3 scan ----
        float vx[ITEMS], vy[ITEMS], vz[ITEMS];
        float ax = 0.f, ay = 0.f, az = 0.f;
        #pragma unroll
        for (int i = 0; i < ITEMS; i++) {
            if (i < nvalid && !((tmask >> i) & 1u)) {
                const int k = kbase + (int)((c_packed >> (4 * i)) & 15u);
                const float* e = erow + (size_t)k * 3;
                const float sp = ((s0mask >> i) & 1u) ? sp0 : sp1;
                ax = fmaf(__ldg(e + 0), sp, ax);
                ay = fmaf(__ldg(e + 1), sp, ay);
                az = fmaf(__ldg(e + 2), sp, az);
            }
            vx[i] = ax; vy[i] = ay; vz[i] = az;
        }

        // ---- block scan of per-thread float3 sums ----
        float sx = ax, sy = ay, sz = az;
        #pragma unroll
        for (int d = 1; d < 32; d <<= 1) {
            float tx = __shfl_up_sync(0xffffffffu, sx, d);
            float ty = __shfl_up_sync(0xffffffffu, sy, d);
            float tz = __shfl_up_sync(0xffffffffu, sz, d);
            if (lane >= d) { sx += tx; sy += ty; sz += tz; }
        }
        if (lane == 31) { s_wx[buf][wid] = sx; s_wy[buf][wid] = sy; s_wz[buf][wid] = sz; }
        __syncthreads();
        if (wid == 0) {
            float wx = (lane < NWARPS) ? s_wx[buf][lane] : 0.f;
            float wy = (lane < NWARPS) ? s_wy[buf][lane] : 0.f;
            float wz = (lane < NWARPS) ? s_wz[buf][lane] : 0.f;
            #pragma unroll
            for (int d = 1; d < NWARPS; d <<= 1) {
                float tx = __shfl_up_sync(0xffffffffu, wx, d);
                float ty = __shfl_up_sync(0xffffffffu, wy, d);
                float tz = __shfl_up_sync(0xffffffffu, wz, d);
                if (lane >= d) { wx += tx; wy += ty; wz += tz; }
            }
            if (lane < NWARPS) { s_wx[buf][lane] = wx; s_wy[buf][lane] = wy; s_wz[buf][lane] = wz; }
        }
        __syncthreads();
        float ex = carry_x + (sx - ax);
        float ey = carry_y + (sy - ay);
        float ez = carry_z + (sz - az);
        if (wid) {
            ex += s_wx[buf][wid - 1];
            ey += s_wy[buf][wid - 1];
            ez += s_wz[buf][wid - 1];
        }
        const float totx = s_wx[buf][NWARPS - 1];
        const float toty = s_wy[buf][NWARPS - 1];
        const float totz = s_wz[buf][NWARPS - 1];

        // ---- write output: 24 contiguous floats per thread (6x float4, streaming) ----
        if (nvalid == ITEMS) {
            float4* q = reinterpret_cast<float4*>(xrow + (size_t)t0 * 3);
            #pragma unroll
            for (int g = 0; g < 6; g++) {
                float o[4];
                #pragma unroll
                for (int j = 0; j < 4; j++) {
                    const int f = g * 4 + j;     // flat float index 0..23
                    const int i = f / 3;         // item
                    const int d = f % 3;         // component
                    const float base_c = (d == 0) ? ox : (d == 1) ? oy : oz;
                    const float off_c  = (d == 0) ? ex : (d == 1) ? ey : ez;
                    const float v_c    = (d == 0) ? vx[i] : (d == 1) ? vy[i] : vz[i];
                    o[j] = base_c + DT * (off_c + v_c);
                }
                __stwt(q + g, make_float4(o[0], o[1], o[2], o[3]));
            }
        } else {
            #pragma unroll
            for (int i = 0; i < ITEMS; i++) {
                if (i < nvalid) {
                    float* o = xrow + (size_t)(t0 + i) * 3;
                    o[0] = ox + DT * (ex + vx[i]);
                    o[1] = oy + DT * (ey + vy[i]);
                    o[2] = oz + DT * (ez + vz[i]);
                }
            }
        }

        carry_k += tile_tum;
        carry_x += totx; carry_y += toty; carry_z += totz;
        // no trailing sync: parity-buffered smem makes next iter's writes safe
    }
}

extern "C" void kernel_launch(void* const* d_in, const int* in_sizes, int n_in,
                              void* d_out, int out_size)
{
    const int*   states = (const int*)  d_in[0];
    const float* e0s    = (const float*)d_in[1];
    const float* sp0    = (const float*)d_in[2];
    const float* sp1    = (const float*)d_in[3];
    const float* x0     = (const float*)d_in[4];
    float*       X      = (float*)d_out;

    const int B = in_sizes[2];           // speed_0 has B elements
    const int T = in_sizes[0] / B;       // states is (B, T)

    traj_scan_kernel<<<B, THREADS>>>(states, e0s, sp0, sp1, x0, X, T);
}

// round 6
// speedup vs baseline: 2.3392x; 1.1034x over previous
#include <cuda_runtime.h>
#include <cuda_bf16.h>

#define THREADS 256
#define ITEMS   8
#define CHUNK   (THREADS * ITEMS)   // 2048
#define NWARPS  (THREADS / 32)      // 8

__global__ __launch_bounds__(THREADS, 2)
void traj_scan_kernel(const int*   __restrict__ states,
                      const float* __restrict__ e0s,
                      const float* __restrict__ speed0,
                      const float* __restrict__ speed1,
                      const float* __restrict__ x0,
                      float*       __restrict__ X,
                      int T)
{
    const int b = blockIdx.x;
    const int*   srow = states + (size_t)b * T;
    const float* erow = e0s    + (size_t)b * (T + 1) * 3;
    float*       xrow = X      + (size_t)b * T * 3;

    const float sp0 = speed0[b];
    const float sp1 = speed1[b];
    const float ox = x0[3 * b + 0];
    const float oy = x0[3 * b + 1];
    const float oz = x0[3 * b + 2];
    const float DT = 0.1f;

    __shared__ float4 s_tot[2][NWARPS];   // parity double-buffered warp totals

    const int lane = threadIdx.x & 31;
    const int wid  = threadIdx.x >> 5;
    const int tid  = threadIdx.x;

    // ---------------- helpers (macros keep everything inlined) -------------
    // load 8 states at tbase (+tid*8), zero-padded
    #define LOAD_STATES(tbase, A, B)                                          \
        do {                                                                  \
            const int _t0 = (tbase) + tid * ITEMS;                            \
            if (_t0 + ITEMS <= T) {                                           \
                A = *reinterpret_cast<const int4*>(srow + _t0);               \
                B = *reinterpret_cast<const int4*>(srow + _t0 + 4);           \
            } else {                                                          \
                int _tmp[8] = {0,0,0,0,0,0,0,0};                              \
                _Pragma("unroll")                                             \
                for (int _i = 0; _i < ITEMS; _i++)                            \
                    if (_t0 + _i < T) _tmp[_i] = srow[_t0 + _i];              \
                A = make_int4(_tmp[0], _tmp[1], _tmp[2], _tmp[3]);            \
                B = make_int4(_tmp[4], _tmp[5], _tmp[6], _tmp[7]);            \
            }                                                                 \
        } while (0)

    // masks from a states tile: zm (tumble|invalid -> speed 0), s0 (state==0),
    // cp (4-bit packed inclusive tumble counts), run (thread tumble total)
    #define COMPUTE_MASKS(A, B, tbase, zm, s0m, cp, run)                      \
        do {                                                                  \
            const int _t0 = (tbase) + tid * ITEMS;                            \
            const int _s[8] = { A.x, A.y, A.z, A.w, B.x, B.y, B.z, B.w };     \
            zm = 0; s0m = 0; cp = 0; run = 0;                                 \
            _Pragma("unroll")                                                 \
            for (int _i = 0; _i < ITEMS; _i++) {                              \
                const unsigned _isT = (_s[_i] == 2);                          \
                const unsigned _inv = (_t0 + _i >= T);                        \
                zm  |= (_isT | _inv) << _i;                                   \
                s0m |= (unsigned)(_s[_i] == 0) << _i;                         \
                run += (int)_isT;                                             \
                cp  |= (unsigned)run << (4 * _i);                             \
            }                                                                 \
        } while (0)

    #define ISSUE_GATHERS(kb, cp, g)                                          \
        do {                                                                  \
            _Pragma("unroll")                                                 \
            for (int _i = 0; _i < ITEMS; _i++) {                              \
                const int _k = (kb) + (int)(((cp) >> (4 * _i)) & 15u);        \
                const float* _e = erow + (size_t)_k * 3;                      \
                g[3 * _i + 0] = __ldg(_e + 0);                                \
                g[3 * _i + 1] = __ldg(_e + 1);                                \
                g[3 * _i + 2] = __ldg(_e + 2);                                \
            }                                                                 \
        } while (0)

    // ---------------- prologue: chunk 0 int scan + gather issue ------------
    int4 na, nb;
    LOAD_STATES(0, na, nb);
    unsigned cur_zm, cur_s0, cp0; int run0;
    COMPUTE_MASKS(na, nb, 0, cur_zm, cur_s0, cp0, run0);

    int carry_k;
    float g[24];
    {
        int xs = run0;
        #pragma unroll
        for (int d = 1; d < 32; d <<= 1) {
            int y = __shfl_up_sync(0xffffffffu, xs, d);
            if (lane >= d) xs += y;
        }
        if (lane == 31) s_tot[0][wid] = make_float4(0.f, 0.f, 0.f, (float)xs);
        __syncthreads();
        int wexcl = 0, tot = 0;
        #pragma unroll
        for (int j = 0; j < NWARPS; j++) {
            const int v = (int)s_tot[0][j].w;
            if (j < wid) wexcl += v;
            tot += v;
        }
        const int kbase0 = wexcl + (xs - run0);
        carry_k = tot;
        ISSUE_GATHERS(kbase0, cp0, g);
    }
    if (CHUNK < T) LOAD_STATES(CHUNK, na, nb);   // states for chunk 1

    float carry_x = 0.f, carry_y = 0.f, carry_z = 0.f;
    int parity = 1;

    // ---------------- main loop -------------------------------------------
    for (int base = 0; base < T; base += CHUNK, parity ^= 1) {
        const bool has_next = (base + CHUNK) < T;

        // masks for chunk i+1 (from prefetched states)
        unsigned nzm = 0, ns0 = 0, ncp = 0; int nrun = 0;
        if (has_next) {
            COMPUTE_MASKS(na, nb, base + CHUNK, nzm, ns0, ncp, nrun);
        }
        // prefetch states for chunk i+2
        if (base + 2 * CHUNK < T) LOAD_STATES(base + 2 * CHUNK, na, nb);

        // consume gathers for chunk i -> local inclusive float3 prefix
        float vx[ITEMS], vy[ITEMS], vz[ITEMS];
        float ax = 0.f, ay = 0.f, az = 0.f;
        #pragma unroll
        for (int i = 0; i < ITEMS; i++) {
            const float sp = ((cur_zm >> i) & 1u) ? 0.f
                           : (((cur_s0 >> i) & 1u) ? sp0 : sp1);
            ax = fmaf(g[3 * i + 0], sp, ax);
            ay = fmaf(g[3 * i + 1], sp, ay);
            az = fmaf(g[3 * i + 2], sp, az);
            vx[i] = ax; vy[i] = ay; vz[i] = az;
        }

        // fused block scan of (ax, ay, az, nrun) — ONE barrier
        float sx = ax, sy = ay, sz = az, sr = (float)nrun;
        #pragma unroll
        for (int d = 1; d < 32; d <<= 1) {
            const float tx = __shfl_up_sync(0xffffffffu, sx, d);
            const float ty = __shfl_up_sync(0xffffffffu, sy, d);
            const float tz = __shfl_up_sync(0xffffffffu, sz, d);
            const float tr = __shfl_up_sync(0xffffffffu, sr, d);
            if (lane >= d) { sx += tx; sy += ty; sz += tz; sr += tr; }
        }
        if (lane == 31) s_tot[parity][wid] = make_float4(sx, sy, sz, sr);
        __syncthreads();
        float wxe = 0.f, wye = 0.f, wze = 0.f, wre = 0.f;   // exclusive (j < wid)
        float txs = 0.f, tys = 0.f, tzs = 0.f, trs = 0.f;   // block totals
        #pragma unroll
        for (int j = 0; j < NWARPS; j++) {
            const float4 t = s_tot[parity][j];
            if (j < wid) { wxe += t.x; wye += t.y; wze += t.z; wre += t.w; }
            txs += t.x; tys += t.y; tzs += t.z; trs += t.w;
        }
        const float ex = carry_x + wxe + (sx - ax);
        const float ey = carry_y + wye + (sy - ay);
        const float ez = carry_z + wze + (sz - az);
        const int   kbase_next = carry_k + (int)(wre + sr - (float)nrun);
        carry_k += (int)trs;
        carry_x += txs; carry_y += tys; carry_z += tzs;

        // issue gathers for chunk i+1 (fly during stores + next-iter setup)
        if (has_next) ISSUE_GATHERS(kbase_next, ncp, g);

        // stores for chunk i (streaming)
        const int t0 = base + tid * ITEMS;
        if (t0 + ITEMS <= T) {
            float4* q = reinterpret_cast<float4*>(xrow + (size_t)t0 * 3);
            #pragma unroll
            for (int gg = 0; gg < 6; gg++) {
                float o[4];
                #pragma unroll
                for (int j = 0; j < 4; j++) {
                    const int f = gg * 4 + j;
                    const int i = f / 3;
                    const int d = f % 3;
                    const float bc = (d == 0) ? ox : (d == 1) ? oy : oz;
                    const float oc = (d == 0) ? ex : (d == 1) ? ey : ez;
                    const float vc = (d == 0) ? vx[i] : (d == 1) ? vy[i] : vz[i];
                    o[j] = bc + DT * (oc + vc);
                }
                __stwt(q + gg, make_float4(o[0], o[1], o[2], o[3]));
            }
        } else {
            #pragma unroll
            for (int i = 0; i < ITEMS; i++) {
                if (t0 + i < T) {
                    float* o = xrow + (size_t)(t0 + i) * 3;
                    o[0] = ox + DT * (ex + vx[i]);
                    o[1] = oy + DT * (ey + vy[i]);
                    o[2] = oz + DT * (ez + vz[i]);
                }
            }
        }

        // rotate consume-masks to chunk i+1
        cur_zm = nzm; cur_s0 = ns0;
    }

    #undef LOAD_STATES
    #undef COMPUTE_MASKS
    #undef ISSUE_GATHERS
}

extern "C" void kernel_launch(void* const* d_in, const int* in_sizes, int n_in,
                              void* d_out, int out_size)
{
    const int*   states = (const int*)  d_in[0];
    const float* e0s    = (const float*)d_in[1];
    const float* sp0    = (const float*)d_in[2];
    const float* sp1    = (const float*)d_in[3];
    const float* x0     = (const float*)d_in[4];
    float*       X      = (float*)d_out;

    const int B = in_sizes[2];           // speed_0 has B elements
    const int T = in_sizes[0] / B;       // states is (B, T)

    traj_scan_kernel<<<B, THREADS>>>(states, e0s, sp0, sp1, x0, X, T);
}